// round 13
// baseline (speedup 1.0000x reference)
#include <cuda_runtime.h>
#include <cuda_fp16.h>
#include <cstdint>

// ===========================================================================
// QLinear: y[8192,4096] = x[8192,4096] @ w^T + bias,  w = sum_k kron(a_k,s_k)
//
// R13: decouple ktile barriers via 2 CTAs/SM. R12 (best, 563.9us; GEMM 526us,
// tensor 86.5%) has 1 CTA/SM: every barrier drains the HMMA pipe. Two
// co-resident CTAs with independent barriers fill each other's gaps.
// Config: BM=128 BN=128 BK=64, 3 stages x 32KB = 96KB smem,
// __launch_bounds__(256,2) (<=128 regs), warp grid 2x4, warp tile 64x32,
// A+B frags double-buffered, R12 pipeline (spread cp.async 2 chunks/ks,
// one commit + one barrier + wait_group 1 per ktile).
// Floors: MMA 2048 cyc/CTA-pair-ktile; crossbar 1536 < 2048 OK.
// Risk: reg cap 128 (est ~112+overhead). Spill -> revert to R12.
// ===========================================================================

static constexpr int TOKENS = 8192;
static constexpr int IN_F   = 4096;
static constexpr int OUT_F  = 4096;

static constexpr int BM = 128;
static constexpr int BN = 128;
static constexpr int BK = 64;                        // halfs; 128B rows
static constexpr int STAGES = 3;
static constexpr int KITERS = IN_F / BK;             // 64

static constexpr int ROWB = BK * 2;                  // 128 B per smem row
static constexpr int A_BYTES = BM * ROWB;            // 16 KB
static constexpr int B_BYTES = BN * ROWB;            // 16 KB
static constexpr int STAGE_BYTES = A_BYTES + B_BYTES;      // 32 KB
static constexpr int SMEM_TOTAL  = STAGES * STAGE_BYTES;   // 96 KB

static constexpr float W_SCALE     = 256.0f;
static constexpr float INV_W_SCALE = 1.0f / 256.0f;

__device__ __half g_xh[(size_t)TOKENS * IN_F];   // 64 MB scratch
__device__ __half g_wh[(size_t)OUT_F * IN_F];    // 32 MB scratch

#define DI static __device__ __forceinline__

DI uint32_t smem_u32(const void* p) {
    uint32_t a;
    asm("{ .reg .u64 t; cvta.to.shared.u64 t, %1; cvt.u32.u64 %0, t; }"
        : "=r"(a) : "l"(p));
    return a;
}

#define CP_ASYNC_16(dst, src) \
    asm volatile("cp.async.cg.shared.global [%0], [%1], 16;" \
        :: "r"(dst), "l"(src) : "memory")

#define CP_ASYNC_COMMIT() asm volatile("cp.async.commit_group;" ::: "memory")
#define CP_ASYNC_WAIT1()  asm volatile("cp.async.wait_group 1;" ::: "memory")

#define LDSM_X4(R0, R1, R2, R3, addr) \
    asm volatile("ldmatrix.sync.aligned.m8n8.x4.shared.b16 {%0,%1,%2,%3}, [%4];" \
        : "=r"(R0), "=r"(R1), "=r"(R2), "=r"(R3) : "r"(addr))

#define MMA16816(C, A0, A1, A2, A3, B0, B1) \
    asm volatile("mma.sync.aligned.m16n8k16.row.col.f32.f16.f16.f32 " \
        "{%0,%1,%2,%3}, {%4,%5,%6,%7}, {%8,%9}, {%0,%1,%2,%3};" \
        : "+f"((C)[0]), "+f"((C)[1]), "+f"((C)[2]), "+f"((C)[3]) \
        : "r"(A0), "r"(A1), "r"(A2), "r"(A3), "r"(B0), "r"(B1))

// ------------------------------ fused prep --------------------------------
static constexpr int CONV_BLOCKS = (int)((size_t)TOKENS * IN_F / 4 / 256); // 32768
static constexpr int BW_BLOCKS   = (4 * 1024 * 1024 / 2) / 256;            // 8192

__global__ void prep_kernel(const float* __restrict__ x,
                            const float* __restrict__ a,
                            const float* __restrict__ s) {
    int bid = blockIdx.x;
    if (bid < CONV_BLOCKS) {
        size_t t = (size_t)bid * blockDim.x + threadIdx.x;
        float4 v = reinterpret_cast<const float4*>(x)[t];
        __half2* o = reinterpret_cast<__half2*>(g_xh);
        o[2 * t + 0] = __floats2half2_rn(v.x, v.y);
        o[2 * t + 1] = __floats2half2_rn(v.z, v.w);
    } else {
        uint32_t t = (uint32_t)(bid - CONV_BLOCKS) * blockDim.x + threadIdx.x;
        uint32_t q2 = (t & 511u) * 2u;            // q pair 0..1022
        uint32_t p  = (t >> 9) & 1023u;
        uint32_t j  = t >> 19;                    // 0..3

        float2 sv[4];
#pragma unroll
        for (int k = 0; k < 4; k++)
            sv[k] = *reinterpret_cast<const float2*>(
                s + (size_t)k * 1048576u + p * 1024u + q2);

#pragma unroll
        for (int i = 0; i < 4; i++) {
            float a0 = __ldg(&a[0 * 16 + i * 4 + j]);
            float a1 = __ldg(&a[1 * 16 + i * 4 + j]);
            float a2 = __ldg(&a[2 * 16 + i * 4 + j]);
            float a3 = __ldg(&a[3 * 16 + i * 4 + j]);
            float wx = (a0 * sv[0].x + a1 * sv[1].x +
                        a2 * sv[2].x + a3 * sv[3].x) * W_SCALE;
            float wy = (a0 * sv[0].y + a1 * sv[1].y +
                        a2 * sv[2].y + a3 * sv[3].y) * W_SCALE;
            *reinterpret_cast<__half2*>(
                g_wh + (size_t)(i * 1024 + p) * IN_F + j * 1024 + q2) =
                __floats2half2_rn(wx, wy);
        }
    }
}

// ------------------------------ GEMM kernel -------------------------------
// SMEM rows 128B (8 chunks of 16B); chunk c of row m stored at (c ^ (m&7)).
// Warp grid 2x4: warp (wm 0..1, wn 0..3) computes 64x32.
// 2 CTAs/SM: independent barriers overlap each other's sync gaps.

__global__ __launch_bounds__(256, 2)
void gemm_kernel(const float* __restrict__ bias, float* __restrict__ out) {
    extern __shared__ char smem[];
    const uint32_t sbase = smem_u32(smem);

    const int tid  = threadIdx.x;
    const int lane = tid & 31;
    const int wid  = tid >> 5;
    const int wm   = wid & 1;     // warp row (2)
    const int wn   = wid >> 1;    // warp col (4)
    const int g    = lane >> 3;
    const int r    = lane & 7;

    const int Mtile = blockIdx.x;
    const int Ntile = blockIdx.y;

    const __half* gA = g_xh + (size_t)(Mtile * BM) * IN_F;
    const __half* gB = g_wh + (size_t)(Ntile * BN) * IN_F;

    // --- one 16B-chunk-slice of the fill for tile kt into stage st ---
    // i in 0..7: i<4 -> A slice (1024 chunks), else B slice (1024 chunks)
    auto issue_chunk = [&](int kt, int st, int i) {
        const uint32_t base = sbase + st * STAGE_BYTES;
        if (i < 4) {
            int idx = tid + i * 256;           // 0..1023
            int m = idx >> 3, c = idx & 7;
            uint32_t off = m * ROWB + ((c ^ (m & 7)) << 4);
            CP_ASYNC_16(base + off, gA + (size_t)m * IN_F + kt * BK + c * 8);
        } else {
            int idx = tid + (i - 4) * 256;     // 0..1023
            int n = idx >> 3, c = idx & 7;
            uint32_t off = n * ROWB + ((c ^ (n & 7)) << 4);
            CP_ASYNC_16(base + A_BYTES + off,
                        gB + (size_t)n * IN_F + kt * BK + c * 8);
        }
    };
    auto issue_full = [&](int kt, int st) {
#pragma unroll
        for (int i = 0; i < 8; i++) issue_chunk(kt, st, i);
        CP_ASYNC_COMMIT();
    };

    // --- per-lane ldmatrix row bases ---
    int rowA[4];
    const int cpA = g >> 1;
#pragma unroll
    for (int mi = 0; mi < 4; mi++)
        rowA[mi] = wm * 64 + mi * 16 + (g & 1) * 8 + r;
    int rowB[2];
    const int cpB = g & 1;
#pragma unroll
    for (int tp = 0; tp < 2; tp++)
        rowB[tp] = wn * 32 + tp * 16 + ((g >> 1) & 1) * 8 + r;

    auto load_frags = [&](uint32_t As, uint32_t Bs, int ks,
                          uint32_t (&a)[4][4], uint32_t (&b)[2][4]) {
        const uint32_t chA = (uint32_t)(((2 * ks + cpA) ^ r) << 4);
        const uint32_t chB = (uint32_t)(((2 * ks + cpB) ^ r) << 4);
#pragma unroll
        for (int mi = 0; mi < 4; mi++)
            LDSM_X4(a[mi][0], a[mi][1], a[mi][2], a[mi][3],
                    As + rowA[mi] * ROWB + chA);
#pragma unroll
        for (int tp = 0; tp < 2; tp++)
            LDSM_X4(b[tp][0], b[tp][1], b[tp][2], b[tp][3],
                    Bs + rowB[tp] * ROWB + chB);
    };

    float acc[4][4][4];
#pragma unroll
    for (int mi = 0; mi < 4; mi++)
#pragma unroll
        for (int ni = 0; ni < 4; ni++)
#pragma unroll
            for (int e = 0; e < 4; e++) acc[mi][ni][e] = 0.0f;

    // --- prologue: tiles 0,1 into stages 0,1 ---
    issue_full(0, 0);
    issue_full(1, 1);
    CP_ASYNC_WAIT1();           // tile 0 landed
    __syncthreads();

    uint32_t af[2][4][4], bf[2][2][4];
    load_frags(sbase, sbase + A_BYTES, 0, af[0], bf[0]);

    // --- mainloop: one barrier per ktile, spread prefetch of kt+2 ---
    int s = 0, sP = 2;
    for (int kt = 0; kt < KITERS; kt++) {
        const uint32_t As = sbase + s * STAGE_BYTES;
        const uint32_t Bs = As + A_BYTES;
        const bool pf = (kt + 2 < KITERS);

#pragma unroll
        for (int ks = 0; ks < 4; ks++) {
            const int cur = ks & 1;
            if (ks < 3) load_frags(As, Bs, ks + 1, af[cur ^ 1], bf[cur ^ 1]);
            if (pf) {
                issue_chunk(kt + 2, sP, 2 * ks + 0);
                issue_chunk(kt + 2, sP, 2 * ks + 1);
            }
#pragma unroll
            for (int mi = 0; mi < 4; mi++)
#pragma unroll
                for (int tp = 0; tp < 2; tp++) {
                    MMA16816(acc[mi][tp * 2 + 0],
                             af[cur][mi][0], af[cur][mi][1],
                             af[cur][mi][2], af[cur][mi][3],
                             bf[cur][tp][0], bf[cur][tp][1]);
                    MMA16816(acc[mi][tp * 2 + 1],
                             af[cur][mi][0], af[cur][mi][1],
                             af[cur][mi][2], af[cur][mi][3],
                             bf[cur][tp][2], bf[cur][tp][3]);
                }
        }

        CP_ASYNC_COMMIT();      // one group per ktile (empty in the tail)
        CP_ASYNC_WAIT1();       // tile kt+1 (issued at kt-1) landed
        __syncthreads();        // all warps done reading stage s

        if (++s == STAGES) s = 0;
        if (++sP == STAGES) sP = 0;
        if (kt + 1 < KITERS) {
            const uint32_t As2 = sbase + s * STAGE_BYTES;
            load_frags(As2, As2 + A_BYTES, 0, af[0], bf[0]);
        }
    }

    // --- epilogue: *(1/256) + bias, fp32 out ---
    const int q  = lane >> 2;
    const int cc = (lane & 3) * 2;

    float2 bv[4];
#pragma unroll
    for (int ni = 0; ni < 4; ni++) {
        int n = Ntile * BN + wn * 32 + ni * 8 + cc;
        bv[ni] = *reinterpret_cast<const float2*>(bias + n);
    }

#pragma unroll
    for (int mi = 0; mi < 4; mi++) {
        int m0 = Mtile * BM + wm * 64 + mi * 16 + q;
#pragma unroll
        for (int ni = 0; ni < 4; ni++) {
            int n = Ntile * BN + wn * 32 + ni * 8 + cc;
            float2 v0, v1;
            v0.x = acc[mi][ni][0] * INV_W_SCALE + bv[ni].x;
            v0.y = acc[mi][ni][1] * INV_W_SCALE + bv[ni].y;
            v1.x = acc[mi][ni][2] * INV_W_SCALE + bv[ni].x;
            v1.y = acc[mi][ni][3] * INV_W_SCALE + bv[ni].y;
            *reinterpret_cast<float2*>(out + (size_t)m0 * OUT_F + n) = v0;
            *reinterpret_cast<float2*>(out + (size_t)(m0 + 8) * OUT_F + n) = v1;
        }
    }
}

// ------------------------------ host launch -------------------------------

extern "C" void kernel_launch(void* const* d_in, const int* in_sizes, int n_in,
                              void* d_out, int out_size) {
    const float* x    = (const float*)d_in[0];
    const float* a    = (const float*)d_in[1];
    const float* s    = (const float*)d_in[2];
    const float* bias = (const float*)d_in[3];
    float* out = (float*)d_out;

    prep_kernel<<<CONV_BLOCKS + BW_BLOCKS, 256>>>(x, a, s);

    cudaFuncSetAttribute(gemm_kernel,
                         cudaFuncAttributeMaxDynamicSharedMemorySize,
                         SMEM_TOTAL);
    gemm_kernel<<<dim3(TOKENS / BM, OUT_F / BN, 1), 256, SMEM_TOTAL>>>(bias, out);
}

// round 15
// speedup vs baseline: 1.1610x; 1.1610x over previous
#include <cuda_runtime.h>
#include <cuda_fp16.h>
#include <cstdint>

// ===========================================================================
// QLinear: y[8192,4096] = x[8192,4096] @ w^T + bias,  w = sum_k kron(a_k,s_k)
//
// R14 = R12 (best: 563.9us, GEMM 526us @ tensor 86.5%) + hide the post-
// barrier ks0 LDSM chain (~250 cyc/ktile = the 13.5% tensor idle):
//   STAGES=4 (192KB, 1 CTA/SM). wait_group 1 + barrier at ktile end makes
//   tiles <= kt+2 CTA-visible from the start of iter kt+1, so next-tile ks0
//   frags are loaded DURING ks3 (overlapped with ks3 MMAs), before the
//   barrier -- strictly race-free (unlike 3-stage early-read).
//   Barrier stays at iteration end (R8 showed moving it regresses).
// Config: BM=128 BN=256 BK=64, 8 warps (2x4), warp tile 64x64, double-
// buffered frags, cp.async spread 3 chunks/ks-step. Prep: fused, half2.
// R13 lesson: <=128 regs is infeasible -> occupancy levers closed.
// ===========================================================================

static constexpr int TOKENS = 8192;
static constexpr int IN_F   = 4096;
static constexpr int OUT_F  = 4096;

static constexpr int BM = 128;
static constexpr int BN = 256;
static constexpr int BK = 64;                        // halfs; 128B rows
static constexpr int STAGES = 4;
static constexpr int KITERS = IN_F / BK;             // 64

static constexpr int ROWB = BK * 2;                  // 128 B per smem row
static constexpr int A_BYTES = BM * ROWB;            // 16 KB
static constexpr int B_BYTES = BN * ROWB;            // 32 KB
static constexpr int STAGE_BYTES = A_BYTES + B_BYTES;      // 48 KB
static constexpr int SMEM_TOTAL  = STAGES * STAGE_BYTES;   // 192 KB

static constexpr float W_SCALE     = 256.0f;
static constexpr float INV_W_SCALE = 1.0f / 256.0f;

__device__ __half g_xh[(size_t)TOKENS * IN_F];   // 64 MB scratch
__device__ __half g_wh[(size_t)OUT_F * IN_F];    // 32 MB scratch

#define DI static __device__ __forceinline__

DI uint32_t smem_u32(const void* p) {
    uint32_t a;
    asm("{ .reg .u64 t; cvta.to.shared.u64 t, %1; cvt.u32.u64 %0, t; }"
        : "=r"(a) : "l"(p));
    return a;
}

#define CP_ASYNC_16(dst, src) \
    asm volatile("cp.async.cg.shared.global [%0], [%1], 16;" \
        :: "r"(dst), "l"(src) : "memory")

#define CP_ASYNC_COMMIT() asm volatile("cp.async.commit_group;" ::: "memory")
#define CP_ASYNC_WAIT1()  asm volatile("cp.async.wait_group 1;" ::: "memory")

#define LDSM_X4(R0, R1, R2, R3, addr) \
    asm volatile("ldmatrix.sync.aligned.m8n8.x4.shared.b16 {%0,%1,%2,%3}, [%4];" \
        : "=r"(R0), "=r"(R1), "=r"(R2), "=r"(R3) : "r"(addr))

#define MMA16816(C, A0, A1, A2, A3, B0, B1) \
    asm volatile("mma.sync.aligned.m16n8k16.row.col.f32.f16.f16.f32 " \
        "{%0,%1,%2,%3}, {%4,%5,%6,%7}, {%8,%9}, {%0,%1,%2,%3};" \
        : "+f"((C)[0]), "+f"((C)[1]), "+f"((C)[2]), "+f"((C)[3]) \
        : "r"(A0), "r"(A1), "r"(A2), "r"(A3), "r"(B0), "r"(B1))

// ------------------------------ fused prep --------------------------------
static constexpr int CONV_BLOCKS = (int)((size_t)TOKENS * IN_F / 4 / 256); // 32768
static constexpr int BW_BLOCKS   = (4 * 1024 * 1024 / 2) / 256;            // 8192

__global__ void prep_kernel(const float* __restrict__ x,
                            const float* __restrict__ a,
                            const float* __restrict__ s) {
    int bid = blockIdx.x;
    if (bid < CONV_BLOCKS) {
        size_t t = (size_t)bid * blockDim.x + threadIdx.x;
        float4 v = reinterpret_cast<const float4*>(x)[t];
        __half2* o = reinterpret_cast<__half2*>(g_xh);
        o[2 * t + 0] = __floats2half2_rn(v.x, v.y);
        o[2 * t + 1] = __floats2half2_rn(v.z, v.w);
    } else {
        uint32_t t = (uint32_t)(bid - CONV_BLOCKS) * blockDim.x + threadIdx.x;
        uint32_t q2 = (t & 511u) * 2u;            // q pair 0..1022
        uint32_t p  = (t >> 9) & 1023u;
        uint32_t j  = t >> 19;                    // 0..3

        float2 sv[4];
#pragma unroll
        for (int k = 0; k < 4; k++)
            sv[k] = *reinterpret_cast<const float2*>(
                s + (size_t)k * 1048576u + p * 1024u + q2);

#pragma unroll
        for (int i = 0; i < 4; i++) {
            float a0 = __ldg(&a[0 * 16 + i * 4 + j]);
            float a1 = __ldg(&a[1 * 16 + i * 4 + j]);
            float a2 = __ldg(&a[2 * 16 + i * 4 + j]);
            float a3 = __ldg(&a[3 * 16 + i * 4 + j]);
            float wx = (a0 * sv[0].x + a1 * sv[1].x +
                        a2 * sv[2].x + a3 * sv[3].x) * W_SCALE;
            float wy = (a0 * sv[0].y + a1 * sv[1].y +
                        a2 * sv[2].y + a3 * sv[3].y) * W_SCALE;
            *reinterpret_cast<__half2*>(
                g_wh + (size_t)(i * 1024 + p) * IN_F + j * 1024 + q2) =
                __floats2half2_rn(wx, wy);
        }
    }
}

// ------------------------------ GEMM kernel -------------------------------
// SMEM rows 128B (8 chunks of 16B); chunk c of row m stored at (c ^ (m&7)).
// One barrier per ktile at iteration END; next-tile ks0 frags loaded in ks3.

__global__ __launch_bounds__(256, 1)
void gemm_kernel(const float* __restrict__ bias, float* __restrict__ out) {
    extern __shared__ char smem[];
    const uint32_t sbase = smem_u32(smem);

    const int tid  = threadIdx.x;
    const int lane = tid & 31;
    const int wid  = tid >> 5;
    const int wm   = wid & 1;     // warp row (2)
    const int wn   = wid >> 1;    // warp col (4)
    const int g    = lane >> 3;
    const int r    = lane & 7;

    const int Mtile = blockIdx.x;
    const int Ntile = blockIdx.y;

    const __half* gA = g_xh + (size_t)(Mtile * BM) * IN_F;
    const __half* gB = g_wh + (size_t)(Ntile * BN) * IN_F;

    // --- one 16B-chunk-slice of the fill for tile kt into stage st ---
    // i in 0..11: i<4 -> A slice, else B slice (i-4 in 0..7)
    auto issue_chunk = [&](int kt, int st, int i) {
        const uint32_t base = sbase + st * STAGE_BYTES;
        if (i < 4) {
            int idx = tid + i * 256;           // 0..1023
            int m = idx >> 3, c = idx & 7;
            uint32_t off = m * ROWB + ((c ^ (m & 7)) << 4);
            CP_ASYNC_16(base + off, gA + (size_t)m * IN_F + kt * BK + c * 8);
        } else {
            int idx = tid + (i - 4) * 256;     // 0..2047
            int n = idx >> 3, c = idx & 7;
            uint32_t off = n * ROWB + ((c ^ (n & 7)) << 4);
            CP_ASYNC_16(base + A_BYTES + off,
                        gB + (size_t)n * IN_F + kt * BK + c * 8);
        }
    };
    auto issue_full = [&](int kt, int st) {
#pragma unroll
        for (int i = 0; i < 12; i++) issue_chunk(kt, st, i);
        CP_ASYNC_COMMIT();
    };

    int rowA[4];
    const int cpA = g >> 1;
#pragma unroll
    for (int mi = 0; mi < 4; mi++)
        rowA[mi] = wm * 64 + mi * 16 + (g & 1) * 8 + r;
    int rowB[4];
    const int cpB = g & 1;
#pragma unroll
    for (int tp = 0; tp < 4; tp++)
        rowB[tp] = wn * 64 + tp * 16 + ((g >> 1) & 1) * 8 + r;

    auto load_frags = [&](uint32_t As, uint32_t Bs, int ks,
                          uint32_t (&a)[4][4], uint32_t (&b)[4][4]) {
        const uint32_t chA = (uint32_t)(((2 * ks + cpA) ^ r) << 4);
        const uint32_t chB = (uint32_t)(((2 * ks + cpB) ^ r) << 4);
#pragma unroll
        for (int mi = 0; mi < 4; mi++)
            LDSM_X4(a[mi][0], a[mi][1], a[mi][2], a[mi][3],
                    As + rowA[mi] * ROWB + chA);
#pragma unroll
        for (int tp = 0; tp < 4; tp++)
            LDSM_X4(b[tp][0], b[tp][1], b[tp][2], b[tp][3],
                    Bs + rowB[tp] * ROWB + chB);
    };

    float acc[4][8][4];
#pragma unroll
    for (int mi = 0; mi < 4; mi++)
#pragma unroll
        for (int ni = 0; ni < 8; ni++)
#pragma unroll
            for (int e = 0; e < 4; e++) acc[mi][ni][e] = 0.0f;

    uint32_t af[2][4][4], bf[2][4][4];

    auto mma_block = [&](uint32_t (&a)[4][4], uint32_t (&b)[4][4]) {
#pragma unroll
        for (int mi = 0; mi < 4; mi++)
#pragma unroll
            for (int tp = 0; tp < 4; tp++) {
                MMA16816(acc[mi][tp * 2 + 0],
                         a[mi][0], a[mi][1], a[mi][2], a[mi][3],
                         b[tp][0], b[tp][1]);
                MMA16816(acc[mi][tp * 2 + 1],
                         a[mi][0], a[mi][1], a[mi][2], a[mi][3],
                         b[tp][2], b[tp][3]);
            }
    };

    // --- prologue: tiles 0,1,2 into stages 0,1,2 ---
    issue_full(0, 0);
    issue_full(1, 1);
    issue_full(2, 2);
    CP_ASYNC_WAIT1();           // 3 pending -> <=1: tiles 0,1 retired
    __syncthreads();            // tiles 0,1 now CTA-visible
    load_frags(sbase, sbase + A_BYTES, 0, af[0], bf[0]);

    // --- mainloop ---
    // Invariant at start of iter kt: tiles <= kt+1 are CTA-visible (wait1 +
    // barrier at end of kt-1 retired through tile kt+1). So the ks3 early
    // load of tile kt+1's ks0 frags is strictly safe.
    // Writes: iter-kt issue -> stage (kt+3)%4; reads: kt%4, (kt+1)%4.
    int s = 0, sP = 3;          // consume stage; prefetch stage for kt+3
    for (int kt = 0; kt < KITERS; kt++) {
        const uint32_t As = sbase + s * STAGE_BYTES;
        const uint32_t Bs = As + A_BYTES;
        const bool pf = (kt + 3 < KITERS);

        // ks0
        load_frags(As, Bs, 1, af[1], bf[1]);
        if (pf) {
            issue_chunk(kt + 3, sP, 0); issue_chunk(kt + 3, sP, 1);
            issue_chunk(kt + 3, sP, 2);
        }
        mma_block(af[0], bf[0]);

        // ks1
        load_frags(As, Bs, 2, af[0], bf[0]);
        if (pf) {
            issue_chunk(kt + 3, sP, 3); issue_chunk(kt + 3, sP, 4);
            issue_chunk(kt + 3, sP, 5);
        }
        mma_block(af[1], bf[1]);

        // ks2
        load_frags(As, Bs, 3, af[1], bf[1]);
        if (pf) {
            issue_chunk(kt + 3, sP, 6); issue_chunk(kt + 3, sP, 7);
            issue_chunk(kt + 3, sP, 8);
        }
        mma_block(af[0], bf[0]);

        // ks3: early-load next tile's ks0 (stage s+1; visible since last
        // barrier), overlapped with ks3's MMA block.
        const int s2 = (s + 1 == STAGES) ? 0 : s + 1;
        if (kt + 1 < KITERS) {
            const uint32_t As2 = sbase + s2 * STAGE_BYTES;
            load_frags(As2, As2 + A_BYTES, 0, af[0], bf[0]);
        }
        if (pf) {
            issue_chunk(kt + 3, sP, 9);  issue_chunk(kt + 3, sP, 10);
            issue_chunk(kt + 3, sP, 11);
        }
        mma_block(af[1], bf[1]);

        CP_ASYNC_COMMIT();      // one group per ktile (empty in the tail)
        CP_ASYNC_WAIT1();       // retires through tile kt+2
        __syncthreads();        // publish tile kt+2; old-stage reads done

        s = s2;
        if (++sP == STAGES) sP = 0;
    }

    // --- epilogue: *(1/256) + bias, fp32 out ---
    const int q  = lane >> 2;
    const int cc = (lane & 3) * 2;

    float2 bv[8];
#pragma unroll
    for (int ni = 0; ni < 8; ni++) {
        int n = Ntile * BN + wn * 64 + ni * 8 + cc;
        bv[ni] = *reinterpret_cast<const float2*>(bias + n);
    }

#pragma unroll
    for (int mi = 0; mi < 4; mi++) {
        int m0 = Mtile * BM + wm * 64 + mi * 16 + q;
#pragma unroll
        for (int ni = 0; ni < 8; ni++) {
            int n = Ntile * BN + wn * 64 + ni * 8 + cc;
            float2 v0, v1;
            v0.x = acc[mi][ni][0] * INV_W_SCALE + bv[ni].x;
            v0.y = acc[mi][ni][1] * INV_W_SCALE + bv[ni].y;
            v1.x = acc[mi][ni][2] * INV_W_SCALE + bv[ni].x;
            v1.y = acc[mi][ni][3] * INV_W_SCALE + bv[ni].y;
            *reinterpret_cast<float2*>(out + (size_t)m0 * OUT_F + n) = v0;
            *reinterpret_cast<float2*>(out + (size_t)(m0 + 8) * OUT_F + n) = v1;
        }
    }
}

// ------------------------------ host launch -------------------------------

extern "C" void kernel_launch(void* const* d_in, const int* in_sizes, int n_in,
                              void* d_out, int out_size) {
    const float* x    = (const float*)d_in[0];
    const float* a    = (const float*)d_in[1];
    const float* s    = (const float*)d_in[2];
    const float* bias = (const float*)d_in[3];
    float* out = (float*)d_out;

    prep_kernel<<<CONV_BLOCKS + BW_BLOCKS, 256>>>(x, a, s);

    cudaFuncSetAttribute(gemm_kernel,
                         cudaFuncAttributeMaxDynamicSharedMemorySize,
                         SMEM_TOTAL);
    gemm_kernel<<<dim3(TOKENS / BM, OUT_F / BN, 1), 256, SMEM_TOTAL>>>(bias, out);
}

// round 16
// speedup vs baseline: 1.2301x; 1.0596x over previous
#include <cuda_runtime.h>
#include <cuda_fp16.h>
#include <cstdint>

// ===========================================================================
// QLinear: y[8192,4096] = x[8192,4096] @ w^T + bias,  w = sum_k kron(a_k,s_k)
//
// FINAL = R12 (best measured: 563.9us total; GEMM 526us @ tensor 86.5%).
// Four GEMM restructurings all regressed vs this schedule:
//   R8  mid-loop barrier seam   -> +27us (scheduling/regs)
//   R9  16 warps single-buffer  -> +85us (crossbar burst, tensor 74%)
//   R13 2 CTAs/SM (128-reg cap) -> +128us (spills, tensor 69%)
//   R14 pre-barrier early-load  -> +35us idle (chain lengthening)
// => R12's schedule is the empirical optimum of this family:
//   BM=128 BN=256 BK=64, 8 warps (2x4), warp tile 64x64, 3 stages (144KB),
//   double-buffered frags, cp.async spread 3 chunks/ks-step, ONE
//   {commit, wait_group 1, __syncthreads} per ktile, post-barrier ks0 load.
// Model: fallback HMMA.16816.F32 rt=8/SMSP -> 2048 cyc floor per ktile;
// this runs at ~93% of floor. Prep: fused conv_x ∪ build_w (37us, ~floor).
// Precision: fp16 inputs scaled by 256 (avoids subnormal flush), fp32
// accumulate, epilogue *(1/256)+bias -> rel_err 2.9e-4.
// ===========================================================================

static constexpr int TOKENS = 8192;
static constexpr int IN_F   = 4096;
static constexpr int OUT_F  = 4096;

static constexpr int BM = 128;
static constexpr int BN = 256;
static constexpr int BK = 64;                        // halfs; 128B rows
static constexpr int STAGES = 3;
static constexpr int KITERS = IN_F / BK;             // 64

static constexpr int ROWB = BK * 2;                  // 128 B per smem row
static constexpr int A_BYTES = BM * ROWB;            // 16 KB
static constexpr int B_BYTES = BN * ROWB;            // 32 KB
static constexpr int STAGE_BYTES = A_BYTES + B_BYTES;      // 48 KB
static constexpr int SMEM_TOTAL  = STAGES * STAGE_BYTES;   // 144 KB

static constexpr float W_SCALE     = 256.0f;
static constexpr float INV_W_SCALE = 1.0f / 256.0f;

__device__ __half g_xh[(size_t)TOKENS * IN_F];   // 64 MB scratch
__device__ __half g_wh[(size_t)OUT_F * IN_F];    // 32 MB scratch

#define DI static __device__ __forceinline__

DI uint32_t smem_u32(const void* p) {
    uint32_t a;
    asm("{ .reg .u64 t; cvta.to.shared.u64 t, %1; cvt.u32.u64 %0, t; }"
        : "=r"(a) : "l"(p));
    return a;
}

#define CP_ASYNC_16(dst, src) \
    asm volatile("cp.async.cg.shared.global [%0], [%1], 16;" \
        :: "r"(dst), "l"(src) : "memory")

#define CP_ASYNC_COMMIT() asm volatile("cp.async.commit_group;" ::: "memory")
#define CP_ASYNC_WAIT1()  asm volatile("cp.async.wait_group 1;" ::: "memory")

#define LDSM_X4(R0, R1, R2, R3, addr) \
    asm volatile("ldmatrix.sync.aligned.m8n8.x4.shared.b16 {%0,%1,%2,%3}, [%4];" \
        : "=r"(R0), "=r"(R1), "=r"(R2), "=r"(R3) : "r"(addr))

#define MMA16816(C, A0, A1, A2, A3, B0, B1) \
    asm volatile("mma.sync.aligned.m16n8k16.row.col.f32.f16.f16.f32 " \
        "{%0,%1,%2,%3}, {%4,%5,%6,%7}, {%8,%9}, {%0,%1,%2,%3};" \
        : "+f"((C)[0]), "+f"((C)[1]), "+f"((C)[2]), "+f"((C)[3]) \
        : "r"(A0), "r"(A1), "r"(A2), "r"(A3), "r"(B0), "r"(B1))

// ------------------------------ fused prep --------------------------------
static constexpr int CONV_BLOCKS = (int)((size_t)TOKENS * IN_F / 4 / 256); // 32768
static constexpr int BW_BLOCKS   = (4 * 1024 * 1024 / 2) / 256;            // 8192

__global__ void prep_kernel(const float* __restrict__ x,
                            const float* __restrict__ a,
                            const float* __restrict__ s) {
    int bid = blockIdx.x;
    if (bid < CONV_BLOCKS) {
        size_t t = (size_t)bid * blockDim.x + threadIdx.x;
        float4 v = reinterpret_cast<const float4*>(x)[t];
        __half2* o = reinterpret_cast<__half2*>(g_xh);
        o[2 * t + 0] = __floats2half2_rn(v.x, v.y);
        o[2 * t + 1] = __floats2half2_rn(v.z, v.w);
    } else {
        uint32_t t = (uint32_t)(bid - CONV_BLOCKS) * blockDim.x + threadIdx.x;
        uint32_t q2 = (t & 511u) * 2u;            // q pair 0..1022
        uint32_t p  = (t >> 9) & 1023u;
        uint32_t j  = t >> 19;                    // 0..3

        float2 sv[4];
#pragma unroll
        for (int k = 0; k < 4; k++)
            sv[k] = *reinterpret_cast<const float2*>(
                s + (size_t)k * 1048576u + p * 1024u + q2);

#pragma unroll
        for (int i = 0; i < 4; i++) {
            float a0 = __ldg(&a[0 * 16 + i * 4 + j]);
            float a1 = __ldg(&a[1 * 16 + i * 4 + j]);
            float a2 = __ldg(&a[2 * 16 + i * 4 + j]);
            float a3 = __ldg(&a[3 * 16 + i * 4 + j]);
            float wx = (a0 * sv[0].x + a1 * sv[1].x +
                        a2 * sv[2].x + a3 * sv[3].x) * W_SCALE;
            float wy = (a0 * sv[0].y + a1 * sv[1].y +
                        a2 * sv[2].y + a3 * sv[3].y) * W_SCALE;
            *reinterpret_cast<__half2*>(
                g_wh + (size_t)(i * 1024 + p) * IN_F + j * 1024 + q2) =
                __floats2half2_rn(wx, wy);
        }
    }
}

// ------------------------------ GEMM kernel -------------------------------
// SMEM rows 128B (8 chunks of 16B); chunk c of row m stored at (c ^ (m&7)).
// One __syncthreads per ktile; cp.async spread over ks-steps.

__global__ __launch_bounds__(256, 1)
void gemm_kernel(const float* __restrict__ bias, float* __restrict__ out) {
    extern __shared__ char smem[];
    const uint32_t sbase = smem_u32(smem);

    const int tid  = threadIdx.x;
    const int lane = tid & 31;
    const int wid  = tid >> 5;
    const int wm   = wid & 1;     // warp row (2)
    const int wn   = wid >> 1;    // warp col (4)
    const int g    = lane >> 3;
    const int r    = lane & 7;

    const int Mtile = blockIdx.x;
    const int Ntile = blockIdx.y;

    const __half* gA = g_xh + (size_t)(Mtile * BM) * IN_F;
    const __half* gB = g_wh + (size_t)(Ntile * BN) * IN_F;

    auto issue_chunk = [&](int kt, int st, int i) {
        const uint32_t base = sbase + st * STAGE_BYTES;
        if (i < 4) {
            int idx = tid + i * 256;           // 0..1023
            int m = idx >> 3, c = idx & 7;
            uint32_t off = m * ROWB + ((c ^ (m & 7)) << 4);
            CP_ASYNC_16(base + off, gA + (size_t)m * IN_F + kt * BK + c * 8);
        } else {
            int idx = tid + (i - 4) * 256;     // 0..2047
            int n = idx >> 3, c = idx & 7;
            uint32_t off = n * ROWB + ((c ^ (n & 7)) << 4);
            CP_ASYNC_16(base + A_BYTES + off,
                        gB + (size_t)n * IN_F + kt * BK + c * 8);
        }
    };
    auto issue_full = [&](int kt, int st) {
#pragma unroll
        for (int i = 0; i < 12; i++) issue_chunk(kt, st, i);
        CP_ASYNC_COMMIT();
    };

    int rowA[4];
    const int cpA = g >> 1;
#pragma unroll
    for (int mi = 0; mi < 4; mi++)
        rowA[mi] = wm * 64 + mi * 16 + (g & 1) * 8 + r;
    int rowB[4];
    const int cpB = g & 1;
#pragma unroll
    for (int tp = 0; tp < 4; tp++)
        rowB[tp] = wn * 64 + tp * 16 + ((g >> 1) & 1) * 8 + r;

    auto load_frags = [&](uint32_t As, uint32_t Bs, int ks,
                          uint32_t (&a)[4][4], uint32_t (&b)[4][4]) {
        const uint32_t chA = (uint32_t)(((2 * ks + cpA) ^ r) << 4);
        const uint32_t chB = (uint32_t)(((2 * ks + cpB) ^ r) << 4);
#pragma unroll
        for (int mi = 0; mi < 4; mi++)
            LDSM_X4(a[mi][0], a[mi][1], a[mi][2], a[mi][3],
                    As + rowA[mi] * ROWB + chA);
#pragma unroll
        for (int tp = 0; tp < 4; tp++)
            LDSM_X4(b[tp][0], b[tp][1], b[tp][2], b[tp][3],
                    Bs + rowB[tp] * ROWB + chB);
    };

    float acc[4][8][4];
#pragma unroll
    for (int mi = 0; mi < 4; mi++)
#pragma unroll
        for (int ni = 0; ni < 8; ni++)
#pragma unroll
            for (int e = 0; e < 4; e++) acc[mi][ni][e] = 0.0f;

    // --- prologue: tiles 0,1 into stages 0,1 ---
    issue_full(0, 0);
    issue_full(1, 1);
    CP_ASYNC_WAIT1();           // tile 0 landed
    __syncthreads();

    uint32_t af[2][4][4], bf[2][4][4];
    load_frags(sbase, sbase + A_BYTES, 0, af[0], bf[0]);

    // --- mainloop: one barrier per ktile, spread prefetch of kt+2 ---
    int s = 0, sP = 2;
    for (int kt = 0; kt < KITERS; kt++) {
        const uint32_t As = sbase + s * STAGE_BYTES;
        const uint32_t Bs = As + A_BYTES;
        const bool pf = (kt + 2 < KITERS);

#pragma unroll
        for (int ks = 0; ks < 4; ks++) {
            const int cur = ks & 1;
            if (ks < 3) load_frags(As, Bs, ks + 1, af[cur ^ 1], bf[cur ^ 1]);
            if (pf) {
                issue_chunk(kt + 2, sP, 3 * ks + 0);
                issue_chunk(kt + 2, sP, 3 * ks + 1);
                issue_chunk(kt + 2, sP, 3 * ks + 2);
            }
#pragma unroll
            for (int mi = 0; mi < 4; mi++)
#pragma unroll
                for (int tp = 0; tp < 4; tp++) {
                    MMA16816(acc[mi][tp * 2 + 0],
                             af[cur][mi][0], af[cur][mi][1],
                             af[cur][mi][2], af[cur][mi][3],
                             bf[cur][tp][0], bf[cur][tp][1]);
                    MMA16816(acc[mi][tp * 2 + 1],
                             af[cur][mi][0], af[cur][mi][1],
                             af[cur][mi][2], af[cur][mi][3],
                             bf[cur][tp][2], bf[cur][tp][3]);
                }
        }

        CP_ASYNC_COMMIT();      // one group per ktile (empty in the tail)
        CP_ASYNC_WAIT1();       // tile kt+1 (issued at kt-1) landed
        __syncthreads();        // all warps done reading stage s

        if (++s == STAGES) s = 0;
        if (++sP == STAGES) sP = 0;
        if (kt + 1 < KITERS) {
            const uint32_t As2 = sbase + s * STAGE_BYTES;
            load_frags(As2, As2 + A_BYTES, 0, af[0], bf[0]);
        }
    }

    // --- epilogue: *(1/256) + bias, fp32 out ---
    const int q  = lane >> 2;
    const int cc = (lane & 3) * 2;

    float2 bv[8];
#pragma unroll
    for (int ni = 0; ni < 8; ni++) {
        int n = Ntile * BN + wn * 64 + ni * 8 + cc;
        bv[ni] = *reinterpret_cast<const float2*>(bias + n);
    }

#pragma unroll
    for (int mi = 0; mi < 4; mi++) {
        int m0 = Mtile * BM + wm * 64 + mi * 16 + q;
#pragma unroll
        for (int ni = 0; ni < 8; ni++) {
            int n = Ntile * BN + wn * 64 + ni * 8 + cc;
            float2 v0, v1;
            v0.x = acc[mi][ni][0] * INV_W_SCALE + bv[ni].x;
            v0.y = acc[mi][ni][1] * INV_W_SCALE + bv[ni].y;
            v1.x = acc[mi][ni][2] * INV_W_SCALE + bv[ni].x;
            v1.y = acc[mi][ni][3] * INV_W_SCALE + bv[ni].y;
            *reinterpret_cast<float2*>(out + (size_t)m0 * OUT_F + n) = v0;
            *reinterpret_cast<float2*>(out + (size_t)(m0 + 8) * OUT_F + n) = v1;
        }
    }
}

// ------------------------------ host launch -------------------------------

extern "C" void kernel_launch(void* const* d_in, const int* in_sizes, int n_in,
                              void* d_out, int out_size) {
    const float* x    = (const float*)d_in[0];
    const float* a    = (const float*)d_in[1];
    const float* s    = (const float*)d_in[2];
    const float* bias = (const float*)d_in[3];
    float* out = (float*)d_out;

    prep_kernel<<<CONV_BLOCKS + BW_BLOCKS, 256>>>(x, a, s);

    cudaFuncSetAttribute(gemm_kernel,
                         cudaFuncAttributeMaxDynamicSharedMemorySize,
                         SMEM_TOTAL);
    gemm_kernel<<<dim3(TOKENS / BM, OUT_F / BN, 1), 256, SMEM_TOTAL>>>(bias, out);
}